// round 5
// baseline (speedup 1.0000x reference)
#include <cuda_runtime.h>

#define NN  50000
#define EE  1600000
#define FIN 128
#define HH  32
#define CC  16

typedef unsigned long long u64;

// ---- scratch (device globals; no allocation allowed) ----
__device__ float g_deg[NN];
__device__ float g_dinv[NN];
__device__ float g_xws[NN * HH];   // dinv-prescaled features (both layers)
__device__ float g_agg[NN * HH];   // aggregation accumulator

// ---- f32x2 helpers ----
__device__ __forceinline__ u64 fma2(u64 a, u64 b, u64 c) {
    u64 d; asm("fma.rn.f32x2 %0, %1, %2, %3;" : "=l"(d) : "l"(a), "l"(b), "l"(c)); return d;
}
__device__ __forceinline__ u64 add2(u64 a, u64 b) {
    u64 d; asm("add.rn.f32x2 %0, %1, %2;" : "=l"(d) : "l"(a), "l"(b)); return d;
}
__device__ __forceinline__ u64 pack2(float x, float y) {
    u64 d; asm("mov.b64 %0, {%1, %2};" : "=l"(d) : "f"(x), "f"(y)); return d;
}

// ================================================================ degrees
__global__ void k_init_deg() {
    int i = blockIdx.x * blockDim.x + threadIdx.x;
    if (i < NN) g_deg[i] = 1.0f;                 // self-loop
}

__global__ void k_count_deg(const int* __restrict__ dst) {
    int e = blockIdx.x * blockDim.x + threadIdx.x;
    if (e < EE) atomicAdd(&g_deg[dst[e]], 1.0f);
}

__global__ void k_dinv() {
    int i = blockIdx.x * blockDim.x + threadIdx.x;
    if (i < NN) g_dinv[i] = rsqrtf(g_deg[i]);
}

// ================================================================ GEMM1: xws = agg = (x @ W1) * dinv[row]
// W1 in registers (lane = column, 64 u64 k-pairs). x staged 64 rows at a time
// into smem (coalesced LDG.128 / conflict-free STS.128), consumed as broadcast
// LDS.128. f32x2 FMA over the K dimension, 8 accumulator chains.
#define TILE_R 64
__global__ void __launch_bounds__(256) k_gemm1(const float* __restrict__ x,
                                               const float* __restrict__ W1) {
    __shared__ float4 xs[TILE_R][32];      // 32KB
    int tid  = threadIdx.x;
    int lane = tid & 31;
    int warp = tid >> 5;

    // Wreg[t] = (W1[2t][lane], W1[2t+1][lane])
    u64 Wreg[64];
#pragma unroll
    for (int t = 0; t < 64; t++)
        Wreg[t] = pack2(W1[(2 * t) * HH + lane], W1[(2 * t + 1) * HH + lane]);

    for (int base = blockIdx.x * TILE_R; base < NN; base += gridDim.x * TILE_R) {
        __syncthreads();
        // stage 64 rows: thread handles 8 float4s, coalesced
#pragma unroll
        for (int p = 0; p < TILE_R * 32 / 256; p++) {
            int idx = p * 256 + tid;
            int r = idx >> 5, j = idx & 31;
            int gr = base + r;
            float4 v = make_float4(0.f, 0.f, 0.f, 0.f);
            if (gr < NN) v = *(const float4*)(x + gr * FIN + 4 * j);
            xs[r][j] = v;
        }
        __syncthreads();

        // warp-per-row, 8 rows per warp
        for (int rl = warp; rl < TILE_R; rl += 8) {
            int row = base + rl;
            if (row >= NN) break;
            const ulonglong2* xr = (const ulonglong2*)&xs[rl][0];
            u64 acc[8];
#pragma unroll
            for (int q = 0; q < 8; q++) acc[q] = 0ull;
#pragma unroll
            for (int j = 0; j < 32; j++) {
                ulonglong2 pv = xr[j];           // broadcast LDS.128: (x4j,x4j+1),(x4j+2,x4j+3)
                acc[(2 * j) & 7]     = fma2(pv.x, Wreg[2 * j],     acc[(2 * j) & 7]);
                acc[(2 * j + 1) & 7] = fma2(pv.y, Wreg[2 * j + 1], acc[(2 * j + 1) & 7]);
            }
            u64 s0 = add2(acc[0], acc[1]);
            u64 s1 = add2(acc[2], acc[3]);
            u64 s2 = add2(acc[4], acc[5]);
            u64 s3 = add2(acc[6], acc[7]);
            s0 = add2(s0, s1);
            s2 = add2(s2, s3);
            s0 = add2(s0, s2);
            float lo, hi;
            asm("mov.b64 {%0, %1}, %2;" : "=f"(lo), "=f"(hi) : "l"(s0));
            float v = (lo + hi) * g_dinv[row];
            g_xws[row * HH + lane] = v;
            g_agg[row * HH + lane] = v;          // seed with self-loop contribution
        }
    }
}

// ================================================================ edge scatter: agg[dst] += xws[src]
// 8 lanes per edge, each lane one float4, vectorized L2 reduction.
__global__ void k_scatter(const int* __restrict__ src, const int* __restrict__ dst) {
    int idx = blockIdx.x * blockDim.x + threadIdx.x;
    if (idx >= EE * 8) return;
    int e  = idx >> 3;
    int c4 = (idx & 7) << 2;
    int s = __ldg(src + e);
    int d = __ldg(dst + e);
    float4 v = *(const float4*)(g_xws + s * HH + c4);
    float* p = g_agg + d * HH + c4;
    asm volatile("red.global.add.v4.f32 [%0], {%1,%2,%3,%4};"
                 :: "l"(p), "f"(v.x), "f"(v.y), "f"(v.z), "f"(v.w)
                 : "memory");
}

// ================================================================ GEMM2 (layer-1 epilogue fused):
// h = tanh(dinv*agg + b1); xws = agg = (h @ W2) * dinv[row]
__global__ void k_gemm2(const float* __restrict__ b1, const float* __restrict__ W2) {
    __shared__ float Ws[HH * HH];
    int tid = threadIdx.x;
    for (int i = tid; i < HH * HH; i += 256) Ws[i] = W2[i];
    __syncthreads();
    int warp = tid >> 5, lane = tid & 31;
    int row = blockIdx.x * 8 + warp;
    if (row >= NN) return;
    float di = g_dinv[row];
    float h = tanhf(di * g_agg[row * HH + lane] + b1[lane]);
    float acc = 0.0f;
#pragma unroll
    for (int j = 0; j < 32; j++) {
        float hj = __shfl_sync(0xffffffffu, h, j);
        acc += hj * Ws[j * HH + lane];
    }
    float v = acc * di;
    g_xws[row * HH + lane] = v;
    g_agg[row * HH + lane] = v;
}

// ================================================================ layer-2 epilogue + classifier
// h = tanh(dinv*agg + b2) -> out[N*CC ..]; out[0..] = h @ Wc + bc
__global__ void k_fin2(const float* __restrict__ b2, const float* __restrict__ Wc,
                       const float* __restrict__ bc, float* __restrict__ out) {
    __shared__ float Wcs[HH * CC];
    int tid = threadIdx.x;
    for (int i = tid; i < HH * CC; i += 256) Wcs[i] = Wc[i];
    __syncthreads();
    int warp = tid >> 5, lane = tid & 31;
    int row = blockIdx.x * 8 + warp;
    if (row >= NN) return;
    float di = g_dinv[row];
    float h = tanhf(di * g_agg[row * HH + lane] + b2[lane]);
    out[NN * CC + row * HH + lane] = h;      // second output: h [N,32]
    int cl = lane & (CC - 1);
    float acc = bc[cl];
#pragma unroll
    for (int j = 0; j < 32; j++) {
        float hj = __shfl_sync(0xffffffffu, h, j);
        acc += hj * Wcs[j * CC + cl];
    }
    if (lane < CC) out[row * CC + lane] = acc;   // first output: out [N,16]
}

// ================================================================ launch
extern "C" void kernel_launch(void* const* d_in, const int* in_sizes, int n_in,
                              void* d_out, int out_size) {
    const float* x  = (const float*)d_in[0];
    const int*   ei = (const int*)  d_in[1];
    const float* W1 = (const float*)d_in[2];
    const float* b1 = (const float*)d_in[3];
    const float* W2 = (const float*)d_in[4];
    const float* b2 = (const float*)d_in[5];
    const float* Wc = (const float*)d_in[6];
    const float* bc = (const float*)d_in[7];
    const int* src = ei;          // edge_index[0]
    const int* dst = ei + EE;     // edge_index[1]
    float* out = (float*)d_out;

    k_init_deg <<<(NN + 255) / 256, 256>>>();
    k_count_deg<<<(EE + 255) / 256, 256>>>(dst);
    k_dinv     <<<(NN + 255) / 256, 256>>>();

    k_gemm1    <<<296, 256>>>(x, W1);
    k_scatter  <<<(EE * 8 + 255) / 256, 256>>>(src, dst);

    k_gemm2    <<<(NN + 7) / 8, 256>>>(b1, W2);
    k_scatter  <<<(EE * 8 + 255) / 256, 256>>>(src, dst);

    k_fin2     <<<(NN + 7) / 8, 256>>>(b2, Wc, bc, out);
}

// round 6
// speedup vs baseline: 1.5233x; 1.5233x over previous
#include <cuda_runtime.h>

#define NN  50000
#define EE  1600000
#define FIN 128
#define HH  32
#define CC  16

typedef unsigned long long u64;

// ---- scratch (device globals; no allocation allowed) ----
__device__ float g_deg[NN];
__device__ float g_dinv[NN];
__device__ float g_xws[NN * HH];   // dinv-prescaled features (both layers)
__device__ float g_agg[NN * HH];   // aggregation accumulator

// ---- f32x2 helpers ----
__device__ __forceinline__ u64 fma2(u64 a, u64 b, u64 c) {
    u64 d; asm("fma.rn.f32x2 %0, %1, %2, %3;" : "=l"(d) : "l"(a), "l"(b), "l"(c)); return d;
}
__device__ __forceinline__ u64 mul2(u64 a, u64 b) {
    u64 d; asm("mul.rn.f32x2 %0, %1, %2;" : "=l"(d) : "l"(a), "l"(b)); return d;
}
__device__ __forceinline__ u64 pack2(float x, float y) {
    u64 d; asm("mov.b64 %0, {%1, %2};" : "=l"(d) : "f"(x), "f"(y)); return d;
}
__device__ __forceinline__ void unpack2(u64 v, float& lo, float& hi) {
    asm("mov.b64 {%0, %1}, %2;" : "=f"(lo), "=f"(hi) : "l"(v));
}

// ================================================================ degrees
__global__ void k_init_deg() {
    int i = blockIdx.x * blockDim.x + threadIdx.x;
    if (i < NN) g_deg[i] = 1.0f;                 // self-loop
}

__global__ void k_count_deg(const int* __restrict__ dst) {
    int e = blockIdx.x * blockDim.x + threadIdx.x;
    if (e < EE) atomicAdd(&g_deg[dst[e]], 1.0f);
}

__global__ void k_dinv() {
    int i = blockIdx.x * blockDim.x + threadIdx.x;
    if (i < NN) g_dinv[i] = rsqrtf(g_deg[i]);
}

// ================================================================ GEMM1: xws = agg = (x @ W1) * dinv[row]
// Register-tiled: 256 threads -> 128 rows x 32 cols. Thread (tx,ty) computes
// 8 rows x 2 cols as 8 f32x2 accs packed over ROW-pairs:
//   acc[2p+c] = (out[r0+2p][c0+c], out[r0+2p+1][c0+c])
// x operand comes from a transposed smem tile (u64 = natural row-pair),
// W staged duplicated so (w,w) is a direct LDS.128. Zero packs in inner loop.
#define XST 132   // floats per k-row of xsT: 16B-aligned, conflict-light
__global__ void __launch_bounds__(256) k_gemm1(const float* __restrict__ x,
                                               const float* __restrict__ W1) {
    __shared__ u64   Ws2[FIN][HH];     // 32KB: Ws2[k][c] = (W[k][c], W[k][c])
    __shared__ float xsT[32][XST];     // 16.9KB: xsT[k][r] = x[base+r][kt*32+k]

    int tid = threadIdx.x;
    int tx = tid & 15;                 // col-pair 0..15
    int ty = tid >> 4;                 // row-octet 0..15
    int r0 = ty * 8;
    int base = blockIdx.x * 128;

    for (int i = tid; i < FIN * HH; i += 256) {
        float f = W1[i];
        Ws2[i >> 5][i & 31] = pack2(f, f);
    }

    u64 acc[8];
#pragma unroll
    for (int q = 0; q < 8; q++) acc[q] = 0ull;

    for (int kt = 0; kt < 4; kt++) {
        __syncthreads();
        // stage 128 rows x 32 k, transposed. Coalesced LDG.128 in.
#pragma unroll
        for (int p = 0; p < 4; p++) {
            int idx = p * 256 + tid;
            int r = idx >> 3, j = idx & 7;
            int gr = base + r;
            float4 v = make_float4(0.f, 0.f, 0.f, 0.f);
            if (gr < NN) v = *(const float4*)(x + gr * FIN + kt * 32 + j * 4);
            xsT[j * 4 + 0][r] = v.x;
            xsT[j * 4 + 1][r] = v.y;
            xsT[j * 4 + 2][r] = v.z;
            xsT[j * 4 + 3][r] = v.w;
        }
        __syncthreads();
#pragma unroll
        for (int k = 0; k < 32; k++) {
            ulonglong2 wv = *(const ulonglong2*)&Ws2[kt * 32 + k][2 * tx];
            ulonglong2 xa = *(const ulonglong2*)&xsT[k][r0];       // rows r0..r0+3
            ulonglong2 xb = *(const ulonglong2*)&xsT[k][r0 + 4];   // rows r0+4..r0+7
            acc[0] = fma2(xa.x, wv.x, acc[0]);
            acc[1] = fma2(xa.x, wv.y, acc[1]);
            acc[2] = fma2(xa.y, wv.x, acc[2]);
            acc[3] = fma2(xa.y, wv.y, acc[3]);
            acc[4] = fma2(xb.x, wv.x, acc[4]);
            acc[5] = fma2(xb.x, wv.y, acc[5]);
            acc[6] = fma2(xb.y, wv.x, acc[6]);
            acc[7] = fma2(xb.y, wv.y, acc[7]);
        }
    }

    // epilogue: scale by dinv, store to xws and agg (self-loop seed)
#pragma unroll
    for (int p = 0; p < 4; p++) {
        int rA = base + r0 + 2 * p;
        int rB = rA + 1;
        if (rA >= NN) break;
        float dA = g_dinv[rA];
        float dB = (rB < NN) ? g_dinv[rB] : 0.0f;
        u64 dd = pack2(dA, dB);
#pragma unroll
        for (int c = 0; c < 2; c++) {
            u64 v = mul2(acc[2 * p + c], dd);
            float lo, hi;
            unpack2(v, lo, hi);
            int col = 2 * tx + c;
            g_xws[rA * HH + col] = lo;
            g_agg[rA * HH + col] = lo;
            if (rB < NN) {
                g_xws[rB * HH + col] = hi;
                g_agg[rB * HH + col] = hi;
            }
        }
    }
}

// ================================================================ edge scatter: agg[dst] += xws[src]
// 8 lanes per edge, each lane one float4, vectorized L2 reduction.
__global__ void k_scatter(const int* __restrict__ src, const int* __restrict__ dst) {
    int idx = blockIdx.x * blockDim.x + threadIdx.x;
    if (idx >= EE * 8) return;
    int e  = idx >> 3;
    int c4 = (idx & 7) << 2;
    int s = __ldg(src + e);
    int d = __ldg(dst + e);
    float4 v = *(const float4*)(g_xws + s * HH + c4);
    float* p = g_agg + d * HH + c4;
    asm volatile("red.global.add.v4.f32 [%0], {%1,%2,%3,%4};"
                 :: "l"(p), "f"(v.x), "f"(v.y), "f"(v.z), "f"(v.w)
                 : "memory");
}

// ================================================================ GEMM2 (layer-1 epilogue fused):
// h = tanh(dinv*agg + b1); xws = agg = (h @ W2) * dinv[row]
__global__ void k_gemm2(const float* __restrict__ b1, const float* __restrict__ W2) {
    __shared__ float Ws[HH * HH];
    int tid = threadIdx.x;
    for (int i = tid; i < HH * HH; i += 256) Ws[i] = W2[i];
    __syncthreads();
    int warp = tid >> 5, lane = tid & 31;
    int row = blockIdx.x * 8 + warp;
    if (row >= NN) return;
    float di = g_dinv[row];
    float h = tanhf(di * g_agg[row * HH + lane] + b1[lane]);
    float acc = 0.0f;
#pragma unroll
    for (int j = 0; j < 32; j++) {
        float hj = __shfl_sync(0xffffffffu, h, j);
        acc += hj * Ws[j * HH + lane];
    }
    float v = acc * di;
    g_xws[row * HH + lane] = v;
    g_agg[row * HH + lane] = v;
}

// ================================================================ layer-2 epilogue + classifier
// h = tanh(dinv*agg + b2) -> out[N*CC ..]; out[0..] = h @ Wc + bc
__global__ void k_fin2(const float* __restrict__ b2, const float* __restrict__ Wc,
                       const float* __restrict__ bc, float* __restrict__ out) {
    __shared__ float Wcs[HH * CC];
    int tid = threadIdx.x;
    for (int i = tid; i < HH * CC; i += 256) Wcs[i] = Wc[i];
    __syncthreads();
    int warp = tid >> 5, lane = tid & 31;
    int row = blockIdx.x * 8 + warp;
    if (row >= NN) return;
    float di = g_dinv[row];
    float h = tanhf(di * g_agg[row * HH + lane] + b2[lane]);
    out[NN * CC + row * HH + lane] = h;      // second output: h [N,32]
    int cl = lane & (CC - 1);
    float acc = bc[cl];
#pragma unroll
    for (int j = 0; j < 32; j++) {
        float hj = __shfl_sync(0xffffffffu, h, j);
        acc += hj * Wcs[j * CC + cl];
    }
    if (lane < CC) out[row * CC + lane] = acc;   // first output: out [N,16]
}

// ================================================================ launch
extern "C" void kernel_launch(void* const* d_in, const int* in_sizes, int n_in,
                              void* d_out, int out_size) {
    const float* x  = (const float*)d_in[0];
    const int*   ei = (const int*)  d_in[1];
    const float* W1 = (const float*)d_in[2];
    const float* b1 = (const float*)d_in[3];
    const float* W2 = (const float*)d_in[4];
    const float* b2 = (const float*)d_in[5];
    const float* Wc = (const float*)d_in[6];
    const float* bc = (const float*)d_in[7];
    const int* src = ei;          // edge_index[0]
    const int* dst = ei + EE;     // edge_index[1]
    float* out = (float*)d_out;

    k_init_deg <<<(NN + 255) / 256, 256>>>();
    k_count_deg<<<(EE + 255) / 256, 256>>>(dst);
    k_dinv     <<<(NN + 255) / 256, 256>>>();

    k_gemm1    <<<(NN + 127) / 128, 256>>>(x, W1);
    k_scatter  <<<(EE * 8 + 255) / 256, 256>>>(src, dst);

    k_gemm2    <<<(NN + 7) / 8, 256>>>(b1, W2);
    k_scatter  <<<(EE * 8 + 255) / 256, 256>>>(src, dst);

    k_fin2     <<<(NN + 7) / 8, 256>>>(b2, Wc, bc, out);
}